// round 1
// baseline (speedup 1.0000x reference)
#include <cuda_runtime.h>
#include <math_constants.h>

#define NORB   1024
#define NTIMES 1024
#define NFZ    24
#define NKEZ   6
#define NTINT  64
#define NALPHA 512
#define RS     66                       // slab row stride in floats (64 tints + 2 pad)

#define SLAB_FLOATS  (NALPHA * RS)      // 33792
#define STAGE_OFF    SLAB_FLOATS        // byte offset 135168, 16B aligned
#define STAGE_FLOATS (NORB * 4)
#define RED_OFF      (STAGE_OFF + STAGE_FLOATS)
#define RED_INTS     (8 * NTINT)
#define SMEM_BYTES   ((RED_OFF + RED_INTS) * 4)   // 153600 bytes

__global__ __launch_bounds__(256, 1)
void pdet_kernel(const float* __restrict__ alpha,
                 const float* __restrict__ dMag,
                 const float* __restrict__ fZ_vals,
                 const float* __restrict__ kEZ_val,
                 const float* __restrict__ grid,
                 const float* __restrict__ fZs,
                 const float* __restrict__ kEZs,
                 const float* __restrict__ alphas,
                 float* __restrict__ out)
{
    extern __shared__ float sm[];
    float*  slab  = sm;
    float4* stage = (float4*)(sm + STAGE_OFF);
    int*    red   = (int*)(sm + RED_OFF);

    const int t   = blockIdx.x;
    const int tid = threadIdx.x;

    // ---- scalar parameters (all cheap cached loads) ----
    const float a_lo   = alphas[0];
    const float a_hi   = alphas[NALPHA - 1];
    const float la0    = log10f(a_lo);
    const float inv_la = 1.0f / (log10f(alphas[1]) - la0);

    const float lf0    = log10f(fZs[0]);
    const float inv_lf = 1.0f / (log10f(fZs[1]) - lf0);

    const float kv = kEZ_val[0];
    int kez = -1;
    #pragma unroll
    for (int i = 0; i < NKEZ; ++i) kez += (kEZs[i] <= kv) ? 1 : 0;
    kez = max(0, min(kez, NKEZ - 1));

    // ---- fZ bin for this epoch: clip(floor(ind)+1, 0, NFZ-2) ----
    float find = (log10f(fZ_vals[t]) - lf0) * inv_lf;
    int f0 = (int)floorf(find) + 1;
    f0 = max(0, min(f0, NFZ - 2));

    // ---- fill slab transposed: slab[a*RS + j] = grid[f0, kez, j, a] ----
    // LDG coalesced (lanes vary a), STS stride 66 floats -> 2-way conflict only.
    const float* src = grid + ((size_t)(f0 * NKEZ + kez) * NTINT) * NALPHA;
    #pragma unroll 4
    for (int idx = tid; idx < NTINT * NALPHA; idx += 256) {
        int j = idx >> 9;            // / NALPHA
        int a = idx & (NALPHA - 1);
        slab[a * RS + j] = src[j * NALPHA + a];
    }

    // ---- stage per-orbit scalars (strided loads, L2-resident after wave 1) ----
    #pragma unroll
    for (int o = tid; o < NORB; o += 256) {
        float av = alpha[(size_t)o * NTIMES + t];
        float dm = dMag [(size_t)o * NTIMES + t];
        bool  m  = (av >= a_lo) && (av <= a_hi);
        float aind = (log10f(av) - la0) * inv_la;
        int a0 = (int)aind;                       // trunc toward zero == astype(int32)
        a0 = max(0, min(a0, NALPHA - 1));
        float dal = aind - (float)a0;             // relative to clipped a0 (reference quirk)
        int s = min(a0, NALPHA - 2);              // dynamic_slice clamp
        if (!m) dm = CUDART_INF_F;                // fold geom_mask: inf < dim never true
        stage[o] = make_float4(__int_as_float(s * RS), dal, dm, 0.0f);
    }
    __syncthreads();

    // ---- main loop: warp w handles 128 orbits; lane handles tints (2*lane, 2*lane+1) ----
    const int w     = tid >> 5;
    const int lane  = tid & 31;
    const int jbase = 2 * lane;
    int c0 = 0, c1 = 0;
    const int obeg = w * (NORB / 8);
    #pragma unroll 4
    for (int o = obeg; o < obeg + NORB / 8; ++o) {
        float4 st = stage[o];                       // 16B broadcast LDS
        int   srow = __float_as_int(st.x);
        float dal  = st.y;
        float dm   = st.z;
        float2 g0 = *(const float2*)(slab + srow + jbase);        // conflict-free
        float2 g1 = *(const float2*)(slab + srow + RS + jbase);
        float d0 = fmaf(dal, g1.x - g0.x, g0.x);
        float d1 = fmaf(dal, g1.y - g0.y, g0.y);
        c0 += (dm < d0);
        c1 += (dm < d1);
    }
    red[w * NTINT + jbase]     = c0;
    red[w * NTINT + jbase + 1] = c1;
    __syncthreads();

    // ---- reduce 8 warps' partials, write pdet[t, tint] ----
    if (tid < NTINT) {
        int c = 0;
        #pragma unroll
        for (int ww = 0; ww < 8; ++ww) c += red[ww * NTINT + tid];
        out[t * NTINT + tid] = (float)c * (1.0f / NORB);
    }
}

extern "C" void kernel_launch(void* const* d_in, const int* in_sizes, int n_in,
                              void* d_out, int out_size)
{
    (void)in_sizes; (void)n_in; (void)out_size;
    const float* alpha   = (const float*)d_in[0];
    const float* dMag    = (const float*)d_in[1];
    const float* fZ_vals = (const float*)d_in[2];
    const float* kEZ_val = (const float*)d_in[3];
    const float* grid    = (const float*)d_in[4];
    const float* fZs     = (const float*)d_in[5];
    const float* kEZs    = (const float*)d_in[6];
    const float* alphas  = (const float*)d_in[7];
    float* out = (float*)d_out;

    cudaFuncSetAttribute(pdet_kernel,
                         cudaFuncAttributeMaxDynamicSharedMemorySize, SMEM_BYTES);
    pdet_kernel<<<NTIMES, 256, SMEM_BYTES>>>(alpha, dMag, fZ_vals, kEZ_val,
                                             grid, fZs, kEZs, alphas, out);
}

// round 2
// speedup vs baseline: 1.2827x; 1.2827x over previous
#include <cuda_runtime.h>
#include <math_constants.h>

#define NORB   1024
#define NTIMES 1024
#define NFZ    24
#define NKEZ   6
#define NTINT  64
#define NALPHA 512
#define RS     66                       // slab row stride in floats (64 tints + 2 pad)

#define NTHREADS 512
#define NWARPS   (NTHREADS / 32)        // 16
#define ORB_PER_WARP (NORB / NWARPS)    // 64

#define SLAB_FLOATS  (NALPHA * RS)      // 33792
#define STAGE_OFF    SLAB_FLOATS        // 16B aligned
#define STAGE_FLOATS (NORB * 4)
#define RED_OFF      (STAGE_OFF + STAGE_FLOATS)
#define RED_INTS     (NWARPS * NTINT)   // 1024
#define SMEM_BYTES   ((RED_OFF + RED_INTS) * 4)   // 155648 bytes

__global__ __launch_bounds__(NTHREADS, 1)
void pdet_kernel(const float* __restrict__ alpha,
                 const float* __restrict__ dMag,
                 const float* __restrict__ fZ_vals,
                 const float* __restrict__ kEZ_val,
                 const float* __restrict__ grid,
                 const float* __restrict__ fZs,
                 const float* __restrict__ kEZs,
                 const float* __restrict__ alphas,
                 float* __restrict__ out)
{
    extern __shared__ float sm[];
    float*  slab  = sm;
    float4* stage = (float4*)(sm + STAGE_OFF);
    int*    red   = (int*)(sm + RED_OFF);

    const int t   = blockIdx.x;
    const int tid = threadIdx.x;

    // ---- scalar parameters ----
    const float a_lo   = alphas[0];
    const float a_hi   = alphas[NALPHA - 1];
    const float la0    = log10f(a_lo);
    const float inv_la = 1.0f / (log10f(alphas[1]) - la0);

    const float lf0    = log10f(fZs[0]);
    const float inv_lf = 1.0f / (log10f(fZs[1]) - lf0);

    const float kv = kEZ_val[0];
    int kez = -1;
    #pragma unroll
    for (int i = 0; i < NKEZ; ++i) kez += (kEZs[i] <= kv) ? 1 : 0;
    kez = max(0, min(kez, NKEZ - 1));

    // ---- fZ bin for this epoch: clip(floor(ind)+1, 0, NFZ-2) ----
    float find = (log10f(fZ_vals[t]) - lf0) * inv_lf;
    int f0 = (int)floorf(find) + 1;
    f0 = max(0, min(f0, NFZ - 2));

    // ---- fill slab transposed: slab[a*RS + j] = grid[f0, kez, j, a] ----
    const float* src = grid + ((size_t)(f0 * NKEZ + kez) * NTINT) * NALPHA;
    #pragma unroll 4
    for (int idx = tid; idx < NTINT * NALPHA; idx += NTHREADS) {
        int j = idx >> 9;            // / NALPHA
        int a = idx & (NALPHA - 1);
        slab[a * RS + j] = src[j * NALPHA + a];
    }

    // ---- stage per-orbit scalars ----
    #pragma unroll
    for (int o = tid; o < NORB; o += NTHREADS) {
        float av = alpha[(size_t)o * NTIMES + t];
        float dm = dMag [(size_t)o * NTIMES + t];
        bool  m  = (av >= a_lo) && (av <= a_hi);
        float aind = (log10f(av) - la0) * inv_la;
        int a0 = (int)aind;                       // trunc toward zero == astype(int32)
        a0 = max(0, min(a0, NALPHA - 1));
        float dal = aind - (float)a0;             // dalpha vs clipped a0 (reference quirk)
        int s = min(a0, NALPHA - 2);              // dynamic_slice clamp
        if (!m) dm = CUDART_INF_F;                // geom_mask folded: inf < dim never true
        stage[o] = make_float4(__int_as_float(s * RS), dal, dm, 0.0f);
    }
    __syncthreads();

    // ---- main loop: 16 warps x 64 orbits; lane handles tints (2*lane, 2*lane+1) ----
    const int w     = tid >> 5;
    const int lane  = tid & 31;
    const int jbase = 2 * lane;
    int c0 = 0, c1 = 0;
    const int obeg = w * ORB_PER_WARP;

    #pragma unroll 1
    for (int o = obeg; o < obeg + ORB_PER_WARP; o += 4) {
        // front-batch the dependency-chain heads (4 independent broadcast LDS.128)
        float4 st0 = stage[o + 0];
        float4 st1 = stage[o + 1];
        float4 st2 = stage[o + 2];
        float4 st3 = stage[o + 3];

        const float2* r00 = (const float2*)(slab + __float_as_int(st0.x) + jbase);
        const float2* r10 = (const float2*)(slab + __float_as_int(st1.x) + jbase);
        const float2* r20 = (const float2*)(slab + __float_as_int(st2.x) + jbase);
        const float2* r30 = (const float2*)(slab + __float_as_int(st3.x) + jbase);

        float2 a0v = r00[0], b0v = r00[RS / 2];   // RS even? 66/2=33 float2 stride
        float2 a1v = r10[0], b1v = r10[RS / 2];
        float2 a2v = r20[0], b2v = r20[RS / 2];
        float2 a3v = r30[0], b3v = r30[RS / 2];

        float d;
        d = fmaf(st0.y, b0v.x - a0v.x, a0v.x); c0 += (st0.z < d);
        d = fmaf(st0.y, b0v.y - a0v.y, a0v.y); c1 += (st0.z < d);
        d = fmaf(st1.y, b1v.x - a1v.x, a1v.x); c0 += (st1.z < d);
        d = fmaf(st1.y, b1v.y - a1v.y, a1v.y); c1 += (st1.z < d);
        d = fmaf(st2.y, b2v.x - a2v.x, a2v.x); c0 += (st2.z < d);
        d = fmaf(st2.y, b2v.y - a2v.y, a2v.y); c1 += (st2.z < d);
        d = fmaf(st3.y, b3v.x - a3v.x, a3v.x); c0 += (st3.z < d);
        d = fmaf(st3.y, b3v.y - a3v.y, a3v.y); c1 += (st3.z < d);
    }
    red[w * NTINT + jbase]     = c0;
    red[w * NTINT + jbase + 1] = c1;
    __syncthreads();

    // ---- reduce warps' partials, write pdet[t, tint] ----
    if (tid < NTINT) {
        int c = 0;
        #pragma unroll
        for (int ww = 0; ww < NWARPS; ++ww) c += red[ww * NTINT + tid];
        out[t * NTINT + tid] = (float)c * (1.0f / NORB);
    }
}

extern "C" void kernel_launch(void* const* d_in, const int* in_sizes, int n_in,
                              void* d_out, int out_size)
{
    (void)in_sizes; (void)n_in; (void)out_size;
    const float* alpha   = (const float*)d_in[0];
    const float* dMag    = (const float*)d_in[1];
    const float* fZ_vals = (const float*)d_in[2];
    const float* kEZ_val = (const float*)d_in[3];
    const float* grid    = (const float*)d_in[4];
    const float* fZs     = (const float*)d_in[5];
    const float* kEZs    = (const float*)d_in[6];
    const float* alphas  = (const float*)d_in[7];
    float* out = (float*)d_out;

    cudaFuncSetAttribute(pdet_kernel,
                         cudaFuncAttributeMaxDynamicSharedMemorySize, SMEM_BYTES);
    pdet_kernel<<<NTIMES, NTHREADS, SMEM_BYTES>>>(alpha, dMag, fZ_vals, kEZ_val,
                                                  grid, fZs, kEZs, alphas, out);
}

// round 3
// speedup vs baseline: 1.4474x; 1.1284x over previous
#include <cuda_runtime.h>
#include <math_constants.h>

#define NORB   1024
#define NTIMES 1024
#define NFZ    24
#define NKEZ   6
#define NTINT  64
#define NALPHA 512

#define HTINT  32                       // tints per CTA (half)
#define RS     513                      // slab row stride in floats (odd -> conflict-free columns)

#define NTHREADS 512
#define NWARPS   (NTHREADS / 32)        // 16
#define ORB_PER_WARP (NORB / NWARPS)    // 64

#define SLAB_FLOATS  (HTINT * RS)       // 16416
#define STAGE_OFF    SLAB_FLOATS        // byte 65664, 16B aligned
#define STAGE_FLOATS (NORB * 4)         // 4096
#define RED_OFF      (STAGE_OFF + STAGE_FLOATS)
#define RED_INTS     (NWARPS * HTINT)   // 512
#define SMEM_BYTES   ((RED_OFF + RED_INTS) * 4)   // 84096 bytes -> 2 CTAs/SM

// 16 MB device scratch: per (epoch, orbit): (s, dalpha, dMag_masked, 0)
__device__ float4 g_stage[NTIMES * NORB];

// ---------------- pre-kernel: build transposed stage -----------------------
__global__ __launch_bounds__(1024)
void stage_kernel(const float* __restrict__ alpha,
                  const float* __restrict__ dMag,
                  const float* __restrict__ alphas)
{
    __shared__ float4 tile[32][33];
    const int tx = threadIdx.x, ty = threadIdx.y;
    const int t = blockIdx.x * 32 + tx;            // epoch (coalesced read dim)
    const int o = blockIdx.y * 32 + ty;            // orbit

    const float a_lo   = alphas[0];
    const float a_hi   = alphas[NALPHA - 1];
    const float la0    = log10f(a_lo);
    const float inv_la = 1.0f / (log10f(alphas[1]) - la0);

    float av = alpha[(size_t)o * NTIMES + t];
    float dm = dMag [(size_t)o * NTIMES + t];
    bool  m  = (av >= a_lo) && (av <= a_hi);
    float aind = (log10f(av) - la0) * inv_la;
    int a0 = (int)aind;                            // trunc toward zero == astype(int32)
    a0 = max(0, min(a0, NALPHA - 1));
    float dal = aind - (float)a0;                  // dalpha vs clipped a0 (reference quirk)
    int s = min(a0, NALPHA - 2);                   // dynamic_slice clamp
    if (!m) dm = CUDART_INF_F;                     // geom_mask folded

    tile[ty][tx] = make_float4(__int_as_float(s), dal, dm, 0.0f);
    __syncthreads();

    // transposed write: coalesced over orbit
    const int tw = blockIdx.x * 32 + ty;
    const int ow = blockIdx.y * 32 + tx;
    g_stage[(size_t)tw * NORB + ow] = tile[tx][ty];
}

// ---------------- main kernel: one CTA = (epoch, tint-half) ----------------
__global__ __launch_bounds__(NTHREADS, 2)
void pdet_kernel(const float* __restrict__ fZ_vals,
                 const float* __restrict__ kEZ_val,
                 const float* __restrict__ grid,
                 const float* __restrict__ fZs,
                 const float* __restrict__ kEZs,
                 float* __restrict__ out)
{
    extern __shared__ float sm[];
    float*  slab  = sm;                            // [HTINT][RS]
    float4* stage = (float4*)(sm + STAGE_OFF);     // [NORB]
    int*    red   = (int*)(sm + RED_OFF);          // [NWARPS][HTINT]

    const int t   = blockIdx.x;
    const int h   = blockIdx.y;                    // tint half
    const int tid = threadIdx.x;

    // ---- fZ bin + kEZ index ----
    const float lf0    = log10f(fZs[0]);
    const float inv_lf = 1.0f / (log10f(fZs[1]) - lf0);
    const float kv = kEZ_val[0];
    int kez = -1;
    #pragma unroll
    for (int i = 0; i < NKEZ; ++i) kez += (kEZs[i] <= kv) ? 1 : 0;
    kez = max(0, min(kez, NKEZ - 1));

    float find = (log10f(fZ_vals[t]) - lf0) * inv_lf;
    int f0 = (int)floorf(find) + 1;
    f0 = max(0, min(f0, NFZ - 2));

    // ---- fill slab (native layout, contiguous 64KB source, conflict-free STS) ----
    const float* src = grid
        + ((size_t)(f0 * NKEZ + kez) * NTINT + h * HTINT) * NALPHA;
    #pragma unroll 8
    for (int idx = tid; idx < HTINT * NALPHA; idx += NTHREADS) {
        int j = idx >> 9;                // / NALPHA
        int a = idx & (NALPHA - 1);
        slab[j * RS + a] = src[idx];
    }

    // ---- stage copy (coalesced float4) ----
    const float4* sg = g_stage + (size_t)t * NORB;
    stage[tid]            = sg[tid];
    stage[tid + NTHREADS] = sg[tid + NTHREADS];
    __syncthreads();

    // ---- main loop: warp w -> 64 orbits, lane -> one tint ----
    const int w     = tid >> 5;
    const int lane  = tid & 31;
    const int jbase = lane * RS;
    int c = 0;
    const int obeg = w * ORB_PER_WARP;

    #pragma unroll 2
    for (int o = obeg; o < obeg + ORB_PER_WARP; o += 4) {
        float4 s0 = stage[o + 0];
        float4 s1 = stage[o + 1];
        float4 s2 = stage[o + 2];
        float4 s3 = stage[o + 3];

        const float* p0 = slab + jbase + __float_as_int(s0.x);
        const float* p1 = slab + jbase + __float_as_int(s1.x);
        const float* p2 = slab + jbase + __float_as_int(s2.x);
        const float* p3 = slab + jbase + __float_as_int(s3.x);

        float g00 = p0[0], g01 = p0[1];             // conflict-free columns
        float g10 = p1[0], g11 = p1[1];
        float g20 = p2[0], g21 = p2[1];
        float g30 = p3[0], g31 = p3[1];

        float d;
        d = fmaf(s0.y, g01 - g00, g00); c += (s0.z < d);
        d = fmaf(s1.y, g11 - g10, g10); c += (s1.z < d);
        d = fmaf(s2.y, g21 - g20, g20); c += (s2.z < d);
        d = fmaf(s3.y, g31 - g30, g30); c += (s3.z < d);
    }
    red[w * HTINT + lane] = c;
    __syncthreads();

    // ---- reduce warp partials, write pdet[t, h*32 + tint] ----
    if (tid < HTINT) {
        int csum = 0;
        #pragma unroll
        for (int ww = 0; ww < NWARPS; ++ww) csum += red[ww * HTINT + tid];
        out[t * NTINT + h * HTINT + tid] = (float)csum * (1.0f / NORB);
    }
}

extern "C" void kernel_launch(void* const* d_in, const int* in_sizes, int n_in,
                              void* d_out, int out_size)
{
    (void)in_sizes; (void)n_in; (void)out_size;
    const float* alpha   = (const float*)d_in[0];
    const float* dMag    = (const float*)d_in[1];
    const float* fZ_vals = (const float*)d_in[2];
    const float* kEZ_val = (const float*)d_in[3];
    const float* grid    = (const float*)d_in[4];
    const float* fZs     = (const float*)d_in[5];
    const float* kEZs    = (const float*)d_in[6];
    const float* alphas  = (const float*)d_in[7];
    float* out = (float*)d_out;

    dim3 sgrid(NTIMES / 32, NORB / 32);
    dim3 sblk(32, 32);
    stage_kernel<<<sgrid, sblk>>>(alpha, dMag, alphas);

    cudaFuncSetAttribute(pdet_kernel,
                         cudaFuncAttributeMaxDynamicSharedMemorySize, SMEM_BYTES);
    dim3 mgrid(NTIMES, NTINT / HTINT);
    pdet_kernel<<<mgrid, NTHREADS, SMEM_BYTES>>>(fZ_vals, kEZ_val, grid,
                                                 fZs, kEZs, out);
}

// round 4
// speedup vs baseline: 1.6840x; 1.1635x over previous
#include <cuda_runtime.h>
#include <math_constants.h>

#define NORB   1024
#define NTIMES 1024
#define NFZ    24
#define NKEZ   6
#define NTINT  64
#define NALPHA 512

#define HTINT  32                       // tints per CTA (half)
#define RS     513                      // slab row stride (odd -> conflict-free columns)

#define NTHREADS 512
#define NWARPS   (NTHREADS / 32)        // 16
#define ORB_PER_WARP (NORB / NWARPS)    // 64

#define SLAB_FLOATS  (HTINT * RS)       // 16416
#define SF_OFF       SLAB_FLOATS        // float2 (dal,dm): byte 65664, 16B aligned
#define SF_FLOATS    (NORB * 2)         // 2048 floats = 8KB
#define SS_OFF       (SF_OFF + SF_FLOATS) // u16 s: byte 73856, 16B aligned
#define SS_FLOATS    (NORB / 2)         // 512 floats = 2KB
#define SMEM_FLOATS  (SS_OFF + SS_FLOATS) // 18976
#define SMEM_BYTES   (SMEM_FLOATS * 4)    // 75904 -> 3 CTAs/SM

// device scratch: per (epoch, orbit)
__device__ float2         g_f[NTIMES * NORB];   // (dalpha, dMag_masked)  8 MB
__device__ unsigned short g_s[NTIMES * NORB];   // s index                2 MB

// ---------------- pre-kernel: build transposed stage -----------------------
__global__ __launch_bounds__(1024)
void stage_kernel(const float* __restrict__ alpha,
                  const float* __restrict__ dMag,
                  const float* __restrict__ alphas)
{
    __shared__ float2         tf[32][33];
    __shared__ unsigned short ts[32][33];
    const int tx = threadIdx.x, ty = threadIdx.y;
    const int t = blockIdx.x * 32 + tx;            // epoch (coalesced read dim)
    const int o = blockIdx.y * 32 + ty;            // orbit

    const float a_lo   = alphas[0];
    const float a_hi   = alphas[NALPHA - 1];
    const float la0    = log10f(a_lo);
    const float inv_la = 1.0f / (log10f(alphas[1]) - la0);

    float av = alpha[(size_t)o * NTIMES + t];
    float dm = dMag [(size_t)o * NTIMES + t];
    bool  m  = (av >= a_lo) && (av <= a_hi);
    float aind = (log10f(av) - la0) * inv_la;
    int a0 = (int)aind;                            // trunc toward zero == astype(int32)
    a0 = max(0, min(a0, NALPHA - 1));
    float dal = aind - (float)a0;                  // dalpha vs clipped a0 (reference quirk)
    int s = min(a0, NALPHA - 2);                   // dynamic_slice clamp
    if (!m) dm = CUDART_INF_F;                     // geom_mask folded

    tf[ty][tx] = make_float2(dal, dm);
    ts[ty][tx] = (unsigned short)s;
    __syncthreads();

    // transposed write: coalesced over orbit
    const int tw = blockIdx.x * 32 + ty;
    const int ow = blockIdx.y * 32 + tx;
    g_f[(size_t)tw * NORB + ow] = tf[tx][ty];
    g_s[(size_t)tw * NORB + ow] = ts[tx][ty];
}

// ---------------- main kernel: one CTA = (epoch, tint-half) ----------------
__global__ __launch_bounds__(NTHREADS, 3)
void pdet_kernel(const float* __restrict__ fZ_vals,
                 const float* __restrict__ kEZ_val,
                 const float* __restrict__ grid,
                 const float* __restrict__ fZs,
                 const float* __restrict__ kEZs,
                 float* __restrict__ out)
{
    extern __shared__ float sm[];
    float*  slab = sm;                             // [HTINT][RS]
    float2* sf   = (float2*)(sm + SF_OFF);         // [NORB] (dal, dm)
    uint2*  ssv  = (uint2*)(sm + SS_OFF);          // [NORB/4] packed 4x u16 s

    const int t   = blockIdx.x;
    const int h   = blockIdx.y;                    // tint half
    const int tid = threadIdx.x;

    // ---- fZ bin + kEZ index ----
    const float lf0    = log10f(fZs[0]);
    const float inv_lf = 1.0f / (log10f(fZs[1]) - lf0);
    const float kv = kEZ_val[0];
    int kez = -1;
    #pragma unroll
    for (int i = 0; i < NKEZ; ++i) kez += (kEZs[i] <= kv) ? 1 : 0;
    kez = max(0, min(kez, NKEZ - 1));

    float find = (log10f(fZ_vals[t]) - lf0) * inv_lf;
    int f0 = (int)floorf(find) + 1;
    f0 = max(0, min(f0, NFZ - 2));

    // ---- fill slab (native layout, contiguous 64KB source, conflict-free STS) ----
    const float* src = grid
        + ((size_t)(f0 * NKEZ + kez) * NTINT + h * HTINT) * NALPHA;
    #pragma unroll 8
    for (int idx = tid; idx < HTINT * NALPHA; idx += NTHREADS) {
        int j = idx >> 9;                // / NALPHA
        int a = idx & (NALPHA - 1);
        slab[j * RS + a] = src[idx];
    }

    // ---- stage copy (coalesced) ----
    {
        const float2* gf = g_f + (size_t)t * NORB;
        sf[tid]            = gf[tid];
        sf[tid + NTHREADS] = gf[tid + NTHREADS];
        const uint2* gs = (const uint2*)(g_s + (size_t)t * NORB);
        if (tid < NORB / 4) ssv[tid] = gs[tid];
    }
    __syncthreads();

    // ---- main loop: warp w -> 64 orbits, lane -> one tint ----
    const int w     = tid >> 5;
    const int lane  = tid & 31;
    const float* row = slab + lane * RS;
    int c = 0;
    const int obeg = w * ORB_PER_WARP;

    #pragma unroll 2
    for (int b = 0; b < ORB_PER_WARP / 4; ++b) {
        const int o = obeg + b * 4;
        uint2 sv = ssv[o >> 2];                     // 4x u16 s, one LDS.64 broadcast
        float2 f0v = sf[o + 0];
        float2 f1v = sf[o + 1];
        float2 f2v = sf[o + 2];
        float2 f3v = sf[o + 3];

        const float* p0 = row + (sv.x & 0xFFFFu);
        const float* p1 = row + (sv.x >> 16);
        const float* p2 = row + (sv.y & 0xFFFFu);
        const float* p3 = row + (sv.y >> 16);

        float g00 = p0[0], g01 = p0[1];             // conflict-free columns
        float g10 = p1[0], g11 = p1[1];
        float g20 = p2[0], g21 = p2[1];
        float g30 = p3[0], g31 = p3[1];

        float d;
        d = fmaf(f0v.x, g01 - g00, g00); c += (f0v.y < d);
        d = fmaf(f1v.x, g11 - g10, g10); c += (f1v.y < d);
        d = fmaf(f2v.x, g21 - g20, g20); c += (f2v.y < d);
        d = fmaf(f3v.x, g31 - g30, g30); c += (f3v.y < d);
    }

    // ---- reduce: reuse stage region as red[NWARPS][HTINT] ----
    __syncthreads();                                // all reads of sf/ssv done
    int* red = (int*)(sm + SF_OFF);
    red[w * HTINT + lane] = c;
    __syncthreads();

    if (tid < HTINT) {
        int csum = 0;
        #pragma unroll
        for (int ww = 0; ww < NWARPS; ++ww) csum += red[ww * HTINT + tid];
        out[t * NTINT + h * HTINT + tid] = (float)csum * (1.0f / NORB);
    }
}

extern "C" void kernel_launch(void* const* d_in, const int* in_sizes, int n_in,
                              void* d_out, int out_size)
{
    (void)in_sizes; (void)n_in; (void)out_size;
    const float* alpha   = (const float*)d_in[0];
    const float* dMag    = (const float*)d_in[1];
    const float* fZ_vals = (const float*)d_in[2];
    const float* kEZ_val = (const float*)d_in[3];
    const float* grid    = (const float*)d_in[4];
    const float* fZs     = (const float*)d_in[5];
    const float* kEZs    = (const float*)d_in[6];
    const float* alphas  = (const float*)d_in[7];
    float* out = (float*)d_out;

    dim3 sgrid(NTIMES / 32, NORB / 32);
    dim3 sblk(32, 32);
    stage_kernel<<<sgrid, sblk>>>(alpha, dMag, alphas);

    cudaFuncSetAttribute(pdet_kernel,
                         cudaFuncAttributeMaxDynamicSharedMemorySize, SMEM_BYTES);
    dim3 mgrid(NTIMES, NTINT / HTINT);
    pdet_kernel<<<mgrid, NTHREADS, SMEM_BYTES>>>(fZ_vals, kEZ_val, grid,
                                                 fZs, kEZs, out);
}